// round 7
// baseline (speedup 1.0000x reference)
#include <cuda_runtime.h>
#include <cuda_fp16.h>

#define NODES   50000
#define EDGES   1600000
#define INCH    128
#define HC      128      // HEADS * OUT_CH
#define HEADS   4
#define OUTCH   32
#define NEG     0.2f
#define NSCANB  ((NODES + 1023) / 1024)   // 49

// ---------------- device scratch (no allocs allowed) ----------------
__device__ float g_h[NODES * HC];         // transformed features fp32 [N,128]
__device__ uint2 g_hh[NODES * HC / 4];    // fp16x8 packed copy of h (per lane: 4 ch)
__device__ float g_asrc[NODES * HEADS];   // per-node src attention logits
__device__ float g_adst[NODES * HEADS];   // per-node dst attention logits
__device__ int   g_cnt[NODES];            // in-degree histogram
__device__ int   g_start[NODES];          // CSR start (exclusive prefix)
__device__ int   g_cur[NODES];            // scatter cursors
__device__ int   g_bsum[NSCANB];          // per-block scan sums
__device__ uint4 g_rec[EDGES];            // per-edge record: {src, w01 fp16x2, w23 fp16x2, pad}

// ---------------- K0: zero histogram ----------------
__global__ void k_zero(int n) {
    int i = blockIdx.x * blockDim.x + threadIdx.x;
    int stride = gridDim.x * blockDim.x;
    for (; i < n; i += stride) g_cnt[i] = 0;
}

// ---------------- K1: in-degree histogram ----------------
__global__ void k_hist(const int* __restrict__ dstp, int ecnt) {
    int i = blockIdx.x * blockDim.x + threadIdx.x;
    int stride = gridDim.x * blockDim.x;
    for (; i < ecnt; i += stride)
        atomicAdd(&g_cnt[__ldg(dstp + i)], 1);
}

// ---------------- K2a: per-block exclusive scan ----------------
__global__ void k_scan1(int n) {
    __shared__ int wsum[32];
    int tid = threadIdx.x, lane = tid & 31, wid = tid >> 5;
    int i = blockIdx.x * 1024 + tid;
    int orig = (i < n) ? g_cnt[i] : 0;
    int v = orig;
#pragma unroll
    for (int off = 1; off < 32; off <<= 1) {
        int t = __shfl_up_sync(0xffffffffu, v, off);
        if (lane >= off) v += t;
    }
    if (lane == 31) wsum[wid] = v;
    __syncthreads();
    if (wid == 0) {
        int s = wsum[lane];
#pragma unroll
        for (int off = 1; off < 32; off <<= 1) {
            int t = __shfl_up_sync(0xffffffffu, s, off);
            if (lane >= off) s += t;
        }
        wsum[lane] = s;
    }
    __syncthreads();
    int excl = v - orig + (wid > 0 ? wsum[wid - 1] : 0);
    if (i < n) g_start[i] = excl;
    if (tid == 0) g_bsum[blockIdx.x] = wsum[31];
}

// ---------------- K3: h = x @ W, fused attention dot products ----------------
// (launched 4th so the ncu bound-capture profiles it)
__global__ void k_gemm(const float* __restrict__ x, const float* __restrict__ W,
                       const float* __restrict__ attS, const float* __restrict__ attD,
                       int n) {
    extern __shared__ float sm[];
    float* Ws = sm;                 // [128][128]
    float* xs = sm + INCH * HC;     // [32][128]

    int tid = threadIdx.x;
    for (int i = tid; i < (INCH * HC) / 4; i += 256)
        ((float4*)Ws)[i] = ((const float4*)W)[i];

    int nodeBase = blockIdx.x * 32;
    for (int i = tid; i < (32 * INCH) / 4; i += 256) {
        int node = nodeBase + (i >> 5);
        float4 v = (node < n) ? ((const float4*)x)[node * 32 + (i & 31)]
                              : make_float4(0.f, 0.f, 0.f, 0.f);
        ((float4*)xs)[i] = v;
    }
    __syncthreads();

    int colt = tid & 31;
    int ng   = tid >> 5;
    int head = colt >> 3;

    float4 aS = ((const float4*)attS)[colt];
    float4 aD = ((const float4*)attD)[colt];

    float acc[4][4];
#pragma unroll
    for (int i = 0; i < 4; i++)
#pragma unroll
        for (int j = 0; j < 4; j++) acc[i][j] = 0.f;

    const float* xr = xs + ng * 4 * INCH;
#pragma unroll 8
    for (int k = 0; k < INCH; k++) {
        float4 wv = ((const float4*)Ws)[k * 32 + colt];
#pragma unroll
        for (int i = 0; i < 4; i++) {
            float xv = xr[i * INCH + k];
            acc[i][0] += xv * wv.x;
            acc[i][1] += xv * wv.y;
            acc[i][2] += xv * wv.z;
            acc[i][3] += xv * wv.w;
        }
    }

#pragma unroll
    for (int i = 0; i < 4; i++) {
        int node = nodeBase + ng * 4 + i;
        float ds = acc[i][0] * aS.x + acc[i][1] * aS.y + acc[i][2] * aS.z + acc[i][3] * aS.w;
        float dd = acc[i][0] * aD.x + acc[i][1] * aD.y + acc[i][2] * aD.z + acc[i][3] * aD.w;
#pragma unroll
        for (int off = 1; off < 8; off <<= 1) {
            ds += __shfl_xor_sync(0xffffffffu, ds, off, 8);
            dd += __shfl_xor_sync(0xffffffffu, dd, off, 8);
        }
        if (node < n) {
            ((float4*)g_h)[node * 32 + colt] =
                make_float4(acc[i][0], acc[i][1], acc[i][2], acc[i][3]);
            __half2 lo = __floats2half2_rn(acc[i][0], acc[i][1]);
            __half2 hi = __floats2half2_rn(acc[i][2], acc[i][3]);
            uint2 u;
            u.x = reinterpret_cast<unsigned&>(lo);
            u.y = reinterpret_cast<unsigned&>(hi);
            g_hh[node * 32 + colt] = u;
            if ((colt & 7) == 0) {
                g_asrc[node * HEADS + head] = ds;
                g_adst[node * HEADS + head] = dd;
            }
        }
    }
}

// ---------------- K2b: scan of block sums ----------------
__global__ void k_scan2(int nb) {
    __shared__ int t0;
    int tid = threadIdx.x, lane = tid & 31, w = tid >> 5;
    int orig = (tid < nb) ? g_bsum[tid] : 0;
    int v = orig;
#pragma unroll
    for (int off = 1; off < 32; off <<= 1) {
        int t = __shfl_up_sync(0xffffffffu, v, off);
        if (lane >= off) v += t;
    }
    if (w == 0 && lane == 31) t0 = v;
    __syncthreads();
    int incl = v + (w == 1 ? t0 : 0);
    if (tid < nb) g_bsum[tid] = incl - orig;   // exclusive
}

// ---------------- K2c: add block offsets, init cursors ----------------
__global__ void k_scan3(int n) {
    int i = blockIdx.x * 1024 + threadIdx.x;
    if (i < n) {
        int v = g_start[i] + g_bsum[blockIdx.x];
        g_start[i] = v;
        g_cur[i] = v;
    }
}

// ---------------- K4: scatter edge records (src + fp16 weights) ----------------
__global__ void k_scatter(const int* __restrict__ srcp,
                          const int* __restrict__ dstp, int ecnt) {
    int i = blockIdx.x * blockDim.x + threadIdx.x;
    int stride = gridDim.x * blockDim.x;
    for (; i < ecnt; i += stride) {
        int d = __ldg(dstp + i);
        int s = __ldg(srcp + i);
        float4 as = __ldg(&((const float4*)g_asrc)[s]);
        float4 ad = __ldg(&((const float4*)g_adst)[d]);
        float a0 = as.x + ad.x, a1 = as.y + ad.y;
        float a2 = as.z + ad.z, a3 = as.w + ad.w;
        float w0 = __expf(a0 > 0.f ? a0 : NEG * a0);
        float w1 = __expf(a1 > 0.f ? a1 : NEG * a1);
        float w2 = __expf(a2 > 0.f ? a2 : NEG * a2);
        float w3 = __expf(a3 > 0.f ? a3 : NEG * a3);
        __half2 w01 = __floats2half2_rn(w0, w1);
        __half2 w23 = __floats2half2_rn(w2, w3);
        uint4 rec;
        rec.x = (unsigned)s;
        rec.y = reinterpret_cast<unsigned&>(w01);
        rec.z = reinterpret_cast<unsigned&>(w23);
        rec.w = 0;
        int pos = atomicAdd(&g_cur[d], 1);
        g_rec[pos] = rec;
    }
}

// ---------------- K5: warp-per-dst aggregation + fused epilogue ----------------
__device__ __forceinline__ float rec_w(const uint4& r, int head) {
    unsigned bits = (head < 2) ? r.y : r.z;
    __half2 h2 = reinterpret_cast<__half2&>(bits);
    return (head & 1) ? __high2float(h2) : __low2float(h2);
}

__device__ __forceinline__ void fma_h16(float4& acc, float w, uint2 u) {
    __half2 lo = reinterpret_cast<__half2&>(u.x);
    __half2 hi = reinterpret_cast<__half2&>(u.y);
    float2 f01 = __half22float2(lo);
    float2 f23 = __half22float2(hi);
    acc.x += w * f01.x; acc.y += w * f01.y;
    acc.z += w * f23.x; acc.w += w * f23.y;
}

__global__ void k_agg(float* __restrict__ out, const float* __restrict__ bias,
                      int n) {
    int lane = threadIdx.x & 31;
    int node = (blockIdx.x * blockDim.x + threadIdx.x) >> 5;
    if (node >= n) return;
    int head = lane >> 3;

    int start = __ldg(&g_start[node]);
    int deg   = __ldg(&g_cnt[node]);
    int end   = start + deg;

    float4 acc = make_float4(0.f, 0.f, 0.f, 0.f);
    float ssum = 0.f;

    int e = start;
    for (; e + 8 <= end; e += 8) {
        uint4 r[8];
#pragma unroll
        for (int j = 0; j < 8; j++) r[j] = __ldg(&g_rec[e + j]);
        uint2 u[8];
#pragma unroll
        for (int j = 0; j < 8; j++)
            u[j] = __ldg(&g_hh[(int)r[j].x * 32 + lane]);
#pragma unroll
        for (int j = 0; j < 8; j++) {
            float w = rec_w(r[j], head);
            ssum += w;
            fma_h16(acc, w, u[j]);
        }
    }
    for (; e < end; e++) {
        uint4 r = __ldg(&g_rec[e]);
        uint2 u = __ldg(&g_hh[(int)r.x * 32 + lane]);
        float w = rec_w(r, head);
        ssum += w;
        fma_h16(acc, w, u);
    }

    // self loop in fp32 (largest single weight: keep full precision)
    {
        float a = __ldg(&g_asrc[node * HEADS + head]) +
                  __ldg(&g_adst[node * HEADS + head]);
        float w = __expf(a > 0.f ? a : NEG * a);
        float4 hv = ((const float4*)g_h)[node * 32 + lane];
        ssum += w;
        acc.x += w * hv.x; acc.y += w * hv.y;
        acc.z += w * hv.z; acc.w += w * hv.w;
    }

    float inv = 1.f / ssum;
    float4 b = ((const float4*)bias)[lane];
    float v0 = acc.x * inv + b.x;
    float v1 = acc.y * inv + b.y;
    float v2 = acc.z * inv + b.z;
    float v3 = acc.w * inv + b.w;
    v0 = v0 > 0.f ? v0 : expm1f(v0);
    v1 = v1 > 0.f ? v1 : expm1f(v1);
    v2 = v2 > 0.f ? v2 : expm1f(v2);
    v3 = v3 > 0.f ? v3 : expm1f(v3);
    ((float4*)out)[node * 32 + lane] = make_float4(v0, v1, v2, v3);
}

// ---------------- launch ----------------
extern "C" void kernel_launch(void* const* d_in, const int* in_sizes, int n_in,
                              void* d_out, int out_size) {
    const float* x    = (const float*)d_in[0];
    const int*   ei   = (const int*)d_in[1];      // int32 (jax demotes int64)
    const float* W    = (const float*)d_in[2];
    const float* attS = (const float*)d_in[3];
    const float* attD = (const float*)d_in[4];
    const float* bias = (const float*)d_in[5];
    float*       out  = (float*)d_out;

    int n    = in_sizes[0] / INCH;     // 50000
    int ecnt = in_sizes[1] / 2;        // 1600000
    int nb   = (n + 1023) / 1024;      // 49

    const int smemBytes = (INCH * HC + 32 * INCH) * (int)sizeof(float); // 80KB
    cudaFuncSetAttribute(k_gemm, cudaFuncAttributeMaxDynamicSharedMemorySize,
                         smemBytes);

    // order chosen so the 4th launch (ncu capture point) is k_gemm
    k_zero<<<64, 1024>>>(n);
    k_hist<<<2048, 256>>>(ei + ecnt, ecnt);
    k_scan1<<<nb, 1024>>>(n);
    k_gemm<<<(n + 31) / 32, 256, smemBytes>>>(x, W, attS, attD, n);
    k_scan2<<<1, 64>>>(nb);
    k_scan3<<<nb, 1024>>>(n);
    k_scatter<<<2048, 256>>>(ei, ei + ecnt, ecnt);
    k_agg<<<(n + 7) / 8, 256>>>(out, bias, n);
}

// round 10
// speedup vs baseline: 1.2066x; 1.2066x over previous
#include <cuda_runtime.h>
#include <cuda_fp16.h>

#define NODES   50000
#define EDGES   1600000
#define INCH    128
#define HC      128      // HEADS * OUT_CH
#define HEADS   4
#define OUTCH   32
#define NEG     0.2f
#define NSCANB  ((NODES + 1023) / 1024)   // 49

// ---------------- device scratch (no allocs allowed) ----------------
__device__ uint2 g_hh[NODES * HC / 4];    // fp16x8 packed h (per lane: 4 ch)
__device__ float g_asrc[NODES * HEADS];   // per-node src attention logits
__device__ float g_adst[NODES * HEADS];   // per-node dst attention logits
__device__ int   g_cnt[NODES];            // in-degree histogram
__device__ int   g_start[NODES];          // CSR start (exclusive prefix)
__device__ int   g_cur[NODES];            // scatter cursors
__device__ int   g_bsum[NSCANB];          // per-block scan sums
__device__ int   g_ssrc[EDGES];           // src indices sorted by dst

// ---------------- K0: zero histogram ----------------
__global__ void k_zero(int n) {
    int i = blockIdx.x * blockDim.x + threadIdx.x;
    int stride = gridDim.x * blockDim.x;
    for (; i < n; i += stride) g_cnt[i] = 0;
}

// ---------------- K1: in-degree histogram ----------------
__global__ void k_hist(const int* __restrict__ dstp, int ecnt) {
    int i = blockIdx.x * blockDim.x + threadIdx.x;
    int stride = gridDim.x * blockDim.x;
    for (; i < ecnt; i += stride)
        atomicAdd(&g_cnt[__ldg(dstp + i)], 1);
}

// ---------------- K2a: per-block exclusive scan ----------------
__global__ void k_scan1(int n) {
    __shared__ int wsum[32];
    int tid = threadIdx.x, lane = tid & 31, wid = tid >> 5;
    int i = blockIdx.x * 1024 + tid;
    int orig = (i < n) ? g_cnt[i] : 0;
    int v = orig;
#pragma unroll
    for (int off = 1; off < 32; off <<= 1) {
        int t = __shfl_up_sync(0xffffffffu, v, off);
        if (lane >= off) v += t;
    }
    if (lane == 31) wsum[wid] = v;
    __syncthreads();
    if (wid == 0) {
        int s = wsum[lane];
#pragma unroll
        for (int off = 1; off < 32; off <<= 1) {
            int t = __shfl_up_sync(0xffffffffu, s, off);
            if (lane >= off) s += t;
        }
        wsum[lane] = s;
    }
    __syncthreads();
    int excl = v - orig + (wid > 0 ? wsum[wid - 1] : 0);
    if (i < n) g_start[i] = excl;
    if (tid == 0) g_bsum[blockIdx.x] = wsum[31];
}

// ---------------- K3: h = x @ W (fused attention), low-smem-traffic version ----
// 64-node tile; 8 warps x 8 nodes/warp; lane owns 4 output cols.
// x read as float4 over k (broadcast LDS.128): smem-cyc per FFMA-op = 0.19.
__global__ void k_gemm(const float* __restrict__ x, const float* __restrict__ W,
                       const float* __restrict__ attS, const float* __restrict__ attD,
                       int n) {
    extern __shared__ float sm[];
    float* Ws = sm;                 // [128][128]  64KB
    float* xs = sm + INCH * HC;     // [64][128]   32KB

    int tid = threadIdx.x;
    for (int i = tid; i < (INCH * HC) / 4; i += 256)
        ((float4*)Ws)[i] = ((const float4*)W)[i];

    int nodeBase = blockIdx.x * 64;
    for (int i = tid; i < (64 * INCH) / 4; i += 256) {
        int node = nodeBase + (i >> 5);
        float4 v = (node < n) ? ((const float4*)x)[node * 32 + (i & 31)]
                              : make_float4(0.f, 0.f, 0.f, 0.f);
        ((float4*)xs)[i] = v;
    }
    __syncthreads();

    int colt = tid & 31;
    int ng   = tid >> 5;
    int head = colt >> 3;

    float4 aS = ((const float4*)attS)[colt];
    float4 aD = ((const float4*)attD)[colt];

    float acc[8][4];
#pragma unroll
    for (int i = 0; i < 8; i++)
#pragma unroll
        for (int j = 0; j < 4; j++) acc[i][j] = 0.f;

    const float* xr = xs + ng * 8 * INCH;
    for (int k = 0; k < INCH; k += 4) {
        float4 wv0 = ((const float4*)Ws)[(k + 0) * 32 + colt];
        float4 wv1 = ((const float4*)Ws)[(k + 1) * 32 + colt];
        float4 wv2 = ((const float4*)Ws)[(k + 2) * 32 + colt];
        float4 wv3 = ((const float4*)Ws)[(k + 3) * 32 + colt];
#pragma unroll
        for (int i = 0; i < 8; i++) {
            float4 xv = *(const float4*)&xr[i * INCH + k];
            acc[i][0] += xv.x * wv0.x + xv.y * wv1.x + xv.z * wv2.x + xv.w * wv3.x;
            acc[i][1] += xv.x * wv0.y + xv.y * wv1.y + xv.z * wv2.y + xv.w * wv3.y;
            acc[i][2] += xv.x * wv0.z + xv.y * wv1.z + xv.z * wv2.z + xv.w * wv3.z;
            acc[i][3] += xv.x * wv0.w + xv.y * wv1.w + xv.z * wv2.w + xv.w * wv3.w;
        }
    }

#pragma unroll
    for (int i = 0; i < 8; i++) {
        int node = nodeBase + ng * 8 + i;
        float ds = acc[i][0] * aS.x + acc[i][1] * aS.y + acc[i][2] * aS.z + acc[i][3] * aS.w;
        float dd = acc[i][0] * aD.x + acc[i][1] * aD.y + acc[i][2] * aD.z + acc[i][3] * aD.w;
#pragma unroll
        for (int off = 1; off < 8; off <<= 1) {
            ds += __shfl_xor_sync(0xffffffffu, ds, off, 8);
            dd += __shfl_xor_sync(0xffffffffu, dd, off, 8);
        }
        if (node < n) {
            __half2 lo = __floats2half2_rn(acc[i][0], acc[i][1]);
            __half2 hi = __floats2half2_rn(acc[i][2], acc[i][3]);
            uint2 u;
            u.x = reinterpret_cast<unsigned&>(lo);
            u.y = reinterpret_cast<unsigned&>(hi);
            g_hh[node * 32 + colt] = u;
            if ((colt & 7) == 0) {
                g_asrc[node * HEADS + head] = ds;
                g_adst[node * HEADS + head] = dd;
            }
        }
    }
}

// ---------------- K2b: scan of block sums ----------------
__global__ void k_scan2(int nb) {
    __shared__ int t0;
    int tid = threadIdx.x, lane = tid & 31, w = tid >> 5;
    int orig = (tid < nb) ? g_bsum[tid] : 0;
    int v = orig;
#pragma unroll
    for (int off = 1; off < 32; off <<= 1) {
        int t = __shfl_up_sync(0xffffffffu, v, off);
        if (lane >= off) v += t;
    }
    if (w == 0 && lane == 31) t0 = v;
    __syncthreads();
    int incl = v + (w == 1 ? t0 : 0);
    if (tid < nb) g_bsum[tid] = incl - orig;   // exclusive
}

// ---------------- K2c: add block offsets, init cursors ----------------
__global__ void k_scan3(int n) {
    int i = blockIdx.x * 1024 + threadIdx.x;
    if (i < n) {
        int v = g_start[i] + g_bsum[blockIdx.x];
        g_start[i] = v;
        g_cur[i] = v;
    }
}

// ---------------- K4: scatter src into dst-sorted order (4B/edge) ----------------
__global__ void k_scatter(const int* __restrict__ srcp,
                          const int* __restrict__ dstp, int ecnt) {
    int i = blockIdx.x * blockDim.x + threadIdx.x;
    int stride = gridDim.x * blockDim.x;
    for (; i < ecnt; i += stride) {
        int d = __ldg(dstp + i);
        int s = __ldg(srcp + i);
        int pos = atomicAdd(&g_cur[d], 1);
        g_ssrc[pos] = s;
    }
}

// ---------------- K5: warp-per-dst aggregation + fused epilogue ----------------
__device__ __forceinline__ void fma_h16(float4& acc, float w, uint2 u) {
    __half2 lo = reinterpret_cast<__half2&>(u.x);
    __half2 hi = reinterpret_cast<__half2&>(u.y);
    float2 f01 = __half22float2(lo);
    float2 f23 = __half22float2(hi);
    acc.x += w * f01.x; acc.y += w * f01.y;
    acc.z += w * f23.x; acc.w += w * f23.y;
}

__global__ void k_agg(float* __restrict__ out, const float* __restrict__ bias,
                      int n) {
    int lane = threadIdx.x & 31;
    int node = (blockIdx.x * blockDim.x + threadIdx.x) >> 5;
    if (node >= n) return;
    int head = lane >> 3;

    float aD = __ldg(&g_adst[node * HEADS + head]);
    int start = __ldg(&g_start[node]);
    int deg   = __ldg(&g_cnt[node]);
    int end   = start + deg;

    float4 acc = make_float4(0.f, 0.f, 0.f, 0.f);
    float ssum = 0.f;

    int e = start;
    for (; e + 8 <= end; e += 8) {
        int s[8];
#pragma unroll
        for (int j = 0; j < 8; j++) s[j] = __ldg(&g_ssrc[e + j]);
        float a[8];
#pragma unroll
        for (int j = 0; j < 8; j++)
            a[j] = __ldg(&g_asrc[s[j] * HEADS + head]) + aD;
        uint2 u[8];
#pragma unroll
        for (int j = 0; j < 8; j++)
            u[j] = __ldg(&g_hh[s[j] * 32 + lane]);
#pragma unroll
        for (int j = 0; j < 8; j++) {
            float w = __expf(a[j] > 0.f ? a[j] : NEG * a[j]);
            ssum += w;
            fma_h16(acc, w, u[j]);
        }
    }
    for (; e < end; e++) {
        int s = __ldg(&g_ssrc[e]);
        float a = __ldg(&g_asrc[s * HEADS + head]) + aD;
        float w = __expf(a > 0.f ? a : NEG * a);
        uint2 u = __ldg(&g_hh[s * 32 + lane]);
        ssum += w;
        fma_h16(acc, w, u);
    }

    // self loop (fp16 h like all other edges)
    {
        float a = __ldg(&g_asrc[node * HEADS + head]) + aD;
        float w = __expf(a > 0.f ? a : NEG * a);
        uint2 u = g_hh[node * 32 + lane];
        ssum += w;
        fma_h16(acc, w, u);
    }

    float inv = 1.f / ssum;
    float4 b = ((const float4*)bias)[lane];
    float v0 = acc.x * inv + b.x;
    float v1 = acc.y * inv + b.y;
    float v2 = acc.z * inv + b.z;
    float v3 = acc.w * inv + b.w;
    v0 = v0 > 0.f ? v0 : expm1f(v0);
    v1 = v1 > 0.f ? v1 : expm1f(v1);
    v2 = v2 > 0.f ? v2 : expm1f(v2);
    v3 = v3 > 0.f ? v3 : expm1f(v3);
    ((float4*)out)[node * 32 + lane] = make_float4(v0, v1, v2, v3);
}

// ---------------- launch ----------------
extern "C" void kernel_launch(void* const* d_in, const int* in_sizes, int n_in,
                              void* d_out, int out_size) {
    const float* x    = (const float*)d_in[0];
    const int*   ei   = (const int*)d_in[1];      // int32 (jax demotes int64)
    const float* W    = (const float*)d_in[2];
    const float* attS = (const float*)d_in[3];
    const float* attD = (const float*)d_in[4];
    const float* bias = (const float*)d_in[5];
    float*       out  = (float*)d_out;

    int n    = in_sizes[0] / INCH;     // 50000
    int ecnt = in_sizes[1] / 2;        // 1600000
    int nb   = (n + 1023) / 1024;      // 49

    const int smemBytes = (INCH * HC + 64 * INCH) * (int)sizeof(float); // 96KB
    cudaFuncSetAttribute(k_gemm, cudaFuncAttributeMaxDynamicSharedMemorySize,
                         smemBytes);

    // order chosen so the 4th launch (ncu capture point) is k_gemm
    k_zero<<<64, 1024>>>(n);
    k_hist<<<2048, 256>>>(ei + ecnt, ecnt);
    k_scan1<<<nb, 1024>>>(n);
    k_gemm<<<(n + 63) / 64, 256, smemBytes>>>(x, W, attS, attD, n);
    k_scan2<<<1, 64>>>(nb);
    k_scan3<<<nb, 1024>>>(n);
    k_scatter<<<2048, 256>>>(ei, ei + ecnt, ecnt);
    k_agg<<<(n + 7) / 8, 256>>>(out, bias, n);
}

// round 11
// speedup vs baseline: 1.2590x; 1.0434x over previous
#include <cuda_runtime.h>
#include <cuda_fp16.h>

#define NODES   50000
#define EDGES   1600000
#define INCH    128
#define HC      128      // HEADS * OUT_CH
#define HEADS   4
#define OUTCH   32
#define NEG     0.2f
#define NSCANB  ((NODES + 1023) / 1024)   // 49

// ---------------- device scratch (no allocs allowed) ----------------
__device__ uint2 g_hh[NODES * HC / 4];    // fp16x8 packed h (per lane: 4 ch)
__device__ float g_asrc[NODES * HEADS];   // per-node src attention logits
__device__ float g_adst[NODES * HEADS];   // per-node dst attention logits
__device__ int   g_cnt[NODES];            // in-degree histogram
__device__ int   g_start[NODES];          // CSR start (exclusive prefix)
__device__ int   g_cur[NODES];            // scatter cursors
__device__ int   g_bsum[NSCANB];          // per-block scan sums
__device__ int   g_ssrc[EDGES];           // src indices sorted by dst

// ---------------- packed fp32x2 helpers (FFMA2 — PTX-only, see SASS_QUICKREF) --
__device__ __forceinline__ unsigned long long pack2(float v) {
    unsigned long long r;
    asm("mov.b64 %0, {%1, %2};" : "=l"(r) : "f"(v), "f"(v));
    return r;
}
__device__ __forceinline__ void fma2(unsigned long long& d,
                                     unsigned long long a,
                                     unsigned long long b) {
    asm("fma.rn.f32x2 %0, %1, %2, %3;" : "=l"(d) : "l"(a), "l"(b), "l"(d));
}
__device__ __forceinline__ float2 unpack2(unsigned long long v) {
    float lo, hi;
    asm("mov.b64 {%0, %1}, %2;" : "=f"(lo), "=f"(hi) : "l"(v));
    return make_float2(lo, hi);
}

// ---------------- K0: zero histogram ----------------
__global__ void k_zero(int n) {
    int i = blockIdx.x * blockDim.x + threadIdx.x;
    int stride = gridDim.x * blockDim.x;
    for (; i < n; i += stride) g_cnt[i] = 0;
}

// ---------------- K1: in-degree histogram ----------------
__global__ void k_hist(const int* __restrict__ dstp, int ecnt) {
    int i = blockIdx.x * blockDim.x + threadIdx.x;
    int stride = gridDim.x * blockDim.x;
    for (; i < ecnt; i += stride)
        atomicAdd(&g_cnt[__ldg(dstp + i)], 1);
}

// ---------------- K2a: per-block exclusive scan ----------------
__global__ void k_scan1(int n) {
    __shared__ int wsum[32];
    int tid = threadIdx.x, lane = tid & 31, wid = tid >> 5;
    int i = blockIdx.x * 1024 + tid;
    int orig = (i < n) ? g_cnt[i] : 0;
    int v = orig;
#pragma unroll
    for (int off = 1; off < 32; off <<= 1) {
        int t = __shfl_up_sync(0xffffffffu, v, off);
        if (lane >= off) v += t;
    }
    if (lane == 31) wsum[wid] = v;
    __syncthreads();
    if (wid == 0) {
        int s = wsum[lane];
#pragma unroll
        for (int off = 1; off < 32; off <<= 1) {
            int t = __shfl_up_sync(0xffffffffu, s, off);
            if (lane >= off) s += t;
        }
        wsum[lane] = s;
    }
    __syncthreads();
    int excl = v - orig + (wid > 0 ? wsum[wid - 1] : 0);
    if (i < n) g_start[i] = excl;
    if (tid == 0) g_bsum[blockIdx.x] = wsum[31];
}

// ---------------- K3: h = x @ W via FFMA2 (packed fp32x2), fused attention ----
// 64-node tile; 8 warps x 8 nodes/warp; lane owns 4 cols = 2 packed col-pairs.
// W LDS.128 delivers packed b64 col-pairs directly (zero pack overhead on W);
// x broadcast scalar duplicated with 1 mov.b64 (alu pipe, parallel to fma).
__global__ void k_gemm(const float* __restrict__ x, const float* __restrict__ W,
                       const float* __restrict__ attS, const float* __restrict__ attD,
                       int n) {
    extern __shared__ float sm[];
    float* Ws = sm;                 // [128][128]  64KB
    float* xs = sm + INCH * HC;     // [64][128]   32KB

    int tid = threadIdx.x;
    for (int i = tid; i < (INCH * HC) / 4; i += 256)
        ((float4*)Ws)[i] = ((const float4*)W)[i];

    int nodeBase = blockIdx.x * 64;
    for (int i = tid; i < (64 * INCH) / 4; i += 256) {
        int node = nodeBase + (i >> 5);
        float4 v = (node < n) ? ((const float4*)x)[node * 32 + (i & 31)]
                              : make_float4(0.f, 0.f, 0.f, 0.f);
        ((float4*)xs)[i] = v;
    }
    __syncthreads();

    int colt = tid & 31;
    int ng   = tid >> 5;
    int head = colt >> 3;

    float4 aS = ((const float4*)attS)[colt];
    float4 aD = ((const float4*)attD)[colt];

    // acc[i][0] = packed cols (4c+0, 4c+1); acc[i][1] = (4c+2, 4c+3)
    unsigned long long acc[8][2];
#pragma unroll
    for (int i = 0; i < 8; i++) { acc[i][0] = 0ull; acc[i][1] = 0ull; }

    const float* xr = xs + ng * 8 * INCH;
    for (int k = 0; k < INCH; k += 4) {
        // each ulonglong2 = the two packed col-pairs of W row (k+j) for this lane
        ulonglong2 wv0 = *(const ulonglong2*)(Ws + (k + 0) * HC + colt * 4);
        ulonglong2 wv1 = *(const ulonglong2*)(Ws + (k + 1) * HC + colt * 4);
        ulonglong2 wv2 = *(const ulonglong2*)(Ws + (k + 2) * HC + colt * 4);
        ulonglong2 wv3 = *(const ulonglong2*)(Ws + (k + 3) * HC + colt * 4);
#pragma unroll
        for (int i = 0; i < 8; i++) {
            float4 xv = *(const float4*)&xr[i * INCH + k];
            unsigned long long xd;
            xd = pack2(xv.x); fma2(acc[i][0], xd, wv0.x); fma2(acc[i][1], xd, wv0.y);
            xd = pack2(xv.y); fma2(acc[i][0], xd, wv1.x); fma2(acc[i][1], xd, wv1.y);
            xd = pack2(xv.z); fma2(acc[i][0], xd, wv2.x); fma2(acc[i][1], xd, wv2.y);
            xd = pack2(xv.w); fma2(acc[i][0], xd, wv3.x); fma2(acc[i][1], xd, wv3.y);
        }
    }

#pragma unroll
    for (int i = 0; i < 8; i++) {
        int node = nodeBase + ng * 8 + i;
        float2 c01 = unpack2(acc[i][0]);
        float2 c23 = unpack2(acc[i][1]);
        float a0 = c01.x, a1 = c01.y, a2 = c23.x, a3 = c23.y;
        float ds = a0 * aS.x + a1 * aS.y + a2 * aS.z + a3 * aS.w;
        float dd = a0 * aD.x + a1 * aD.y + a2 * aD.z + a3 * aD.w;
#pragma unroll
        for (int off = 1; off < 8; off <<= 1) {
            ds += __shfl_xor_sync(0xffffffffu, ds, off, 8);
            dd += __shfl_xor_sync(0xffffffffu, dd, off, 8);
        }
        if (node < n) {
            __half2 lo = __floats2half2_rn(a0, a1);
            __half2 hi = __floats2half2_rn(a2, a3);
            uint2 u;
            u.x = reinterpret_cast<unsigned&>(lo);
            u.y = reinterpret_cast<unsigned&>(hi);
            g_hh[node * 32 + colt] = u;
            if ((colt & 7) == 0) {
                g_asrc[node * HEADS + head] = ds;
                g_adst[node * HEADS + head] = dd;
            }
        }
    }
}

// ---------------- K2b: scan of block sums ----------------
__global__ void k_scan2(int nb) {
    __shared__ int t0;
    int tid = threadIdx.x, lane = tid & 31, w = tid >> 5;
    int orig = (tid < nb) ? g_bsum[tid] : 0;
    int v = orig;
#pragma unroll
    for (int off = 1; off < 32; off <<= 1) {
        int t = __shfl_up_sync(0xffffffffu, v, off);
        if (lane >= off) v += t;
    }
    if (w == 0 && lane == 31) t0 = v;
    __syncthreads();
    int incl = v + (w == 1 ? t0 : 0);
    if (tid < nb) g_bsum[tid] = incl - orig;   // exclusive
}

// ---------------- K2c: add block offsets, init cursors ----------------
__global__ void k_scan3(int n) {
    int i = blockIdx.x * 1024 + threadIdx.x;
    if (i < n) {
        int v = g_start[i] + g_bsum[blockIdx.x];
        g_start[i] = v;
        g_cur[i] = v;
    }
}

// ---------------- K4: scatter src into dst-sorted order (4B/edge) ----------------
__global__ void k_scatter(const int* __restrict__ srcp,
                          const int* __restrict__ dstp, int ecnt) {
    int i = blockIdx.x * blockDim.x + threadIdx.x;
    int stride = gridDim.x * blockDim.x;
    for (; i < ecnt; i += stride) {
        int d = __ldg(dstp + i);
        int s = __ldg(srcp + i);
        int pos = atomicAdd(&g_cur[d], 1);
        g_ssrc[pos] = s;
    }
}

// ---------------- K5: warp-per-dst aggregation + fused epilogue ----------------
__device__ __forceinline__ void fma_h16(float4& acc, float w, uint2 u) {
    __half2 lo = reinterpret_cast<__half2&>(u.x);
    __half2 hi = reinterpret_cast<__half2&>(u.y);
    float2 f01 = __half22float2(lo);
    float2 f23 = __half22float2(hi);
    acc.x += w * f01.x; acc.y += w * f01.y;
    acc.z += w * f23.x; acc.w += w * f23.y;
}

__global__ void k_agg(float* __restrict__ out, const float* __restrict__ bias,
                      int n) {
    int lane = threadIdx.x & 31;
    int node = (blockIdx.x * blockDim.x + threadIdx.x) >> 5;
    if (node >= n) return;
    int head = lane >> 3;

    float aD = __ldg(&g_adst[node * HEADS + head]);
    int start = __ldg(&g_start[node]);
    int deg   = __ldg(&g_cnt[node]);
    int end   = start + deg;

    float4 acc = make_float4(0.f, 0.f, 0.f, 0.f);
    float ssum = 0.f;

    int e = start;
    for (; e + 8 <= end; e += 8) {
        int s[8];
#pragma unroll
        for (int j = 0; j < 8; j++) s[j] = __ldg(&g_ssrc[e + j]);
        float a[8];
#pragma unroll
        for (int j = 0; j < 8; j++)
            a[j] = __ldg(&g_asrc[s[j] * HEADS + head]) + aD;
        uint2 u[8];
#pragma unroll
        for (int j = 0; j < 8; j++)
            u[j] = __ldg(&g_hh[s[j] * 32 + lane]);
#pragma unroll
        for (int j = 0; j < 8; j++) {
            float w = __expf(a[j] > 0.f ? a[j] : NEG * a[j]);
            ssum += w;
            fma_h16(acc, w, u[j]);
        }
    }
    for (; e < end; e++) {
        int s = __ldg(&g_ssrc[e]);
        float a = __ldg(&g_asrc[s * HEADS + head]) + aD;
        float w = __expf(a > 0.f ? a : NEG * a);
        uint2 u = __ldg(&g_hh[s * 32 + lane]);
        ssum += w;
        fma_h16(acc, w, u);
    }

    // self loop (fp16 h like all other edges)
    {
        float a = __ldg(&g_asrc[node * HEADS + head]) + aD;
        float w = __expf(a > 0.f ? a : NEG * a);
        uint2 u = g_hh[node * 32 + lane];
        ssum += w;
        fma_h16(acc, w, u);
    }

    float inv = 1.f / ssum;
    float4 b = ((const float4*)bias)[lane];
    float v0 = acc.x * inv + b.x;
    float v1 = acc.y * inv + b.y;
    float v2 = acc.z * inv + b.z;
    float v3 = acc.w * inv + b.w;
    v0 = v0 > 0.f ? v0 : expm1f(v0);
    v1 = v1 > 0.f ? v1 : expm1f(v1);
    v2 = v2 > 0.f ? v2 : expm1f(v2);
    v3 = v3 > 0.f ? v3 : expm1f(v3);
    ((float4*)out)[node * 32 + lane] = make_float4(v0, v1, v2, v3);
}

// ---------------- launch ----------------
extern "C" void kernel_launch(void* const* d_in, const int* in_sizes, int n_in,
                              void* d_out, int out_size) {
    const float* x    = (const float*)d_in[0];
    const int*   ei   = (const int*)d_in[1];      // int32 (jax demotes int64)
    const float* W    = (const float*)d_in[2];
    const float* attS = (const float*)d_in[3];
    const float* attD = (const float*)d_in[4];
    const float* bias = (const float*)d_in[5];
    float*       out  = (float*)d_out;

    int n    = in_sizes[0] / INCH;     // 50000
    int ecnt = in_sizes[1] / 2;        // 1600000
    int nb   = (n + 1023) / 1024;      // 49

    const int smemBytes = (INCH * HC + 64 * INCH) * (int)sizeof(float); // 96KB
    cudaFuncSetAttribute(k_gemm, cudaFuncAttributeMaxDynamicSharedMemorySize,
                         smemBytes);

    // order chosen so the ncu bounded capture lands on k_gemm (4th launch)
    k_zero<<<64, 1024>>>(n);
    k_hist<<<2048, 256>>>(ei + ecnt, ecnt);
    k_scan1<<<nb, 1024>>>(n);
    k_gemm<<<(n + 63) / 64, 256, smemBytes>>>(x, W, attS, attD, n);
    k_scan2<<<1, 64>>>(nb);
    k_scan3<<<nb, 1024>>>(n);
    k_scatter<<<2048, 256>>>(ei, ei + ecnt, ecnt);
    k_agg<<<(n + 7) / 8, 256>>>(out, bias, n);
}

// round 12
// speedup vs baseline: 1.4975x; 1.1895x over previous
#include <cuda_runtime.h>
#include <cuda_fp16.h>

#define NODES   50000
#define EDGES   1600000
#define INCH    128
#define HC      128      // HEADS * OUT_CH
#define HEADS   4
#define OUTCH   32
#define NEG     0.2f
#define NSCANB  ((NODES + 1023) / 1024)   // 49
#define PITCH   136                        // f16 pitch: bank = 4*row+t, conflict-free

// ---------------- device scratch (no allocs allowed) ----------------
__device__ uint2 g_hh[NODES * HC / 4];    // fp16x8 packed h (per lane: 4 ch)
__device__ float g_asrc[NODES * HEADS];   // per-node src attention logits
__device__ float g_adst[NODES * HEADS];   // per-node dst attention logits
__device__ int   g_cnt[NODES];            // in-degree histogram
__device__ int   g_start[NODES];          // CSR start (exclusive prefix)
__device__ int   g_cur[NODES];            // scatter cursors
__device__ int   g_bsum[NSCANB];          // per-block scan sums
__device__ int   g_ssrc[EDGES];           // src indices sorted by dst

// ---------------- K0: zero histogram ----------------
__global__ void k_zero(int n) {
    int i = blockIdx.x * blockDim.x + threadIdx.x;
    int stride = gridDim.x * blockDim.x;
    for (; i < n; i += stride) g_cnt[i] = 0;
}

// ---------------- K1: in-degree histogram ----------------
__global__ void k_hist(const int* __restrict__ dstp, int ecnt) {
    int i = blockIdx.x * blockDim.x + threadIdx.x;
    int stride = gridDim.x * blockDim.x;
    for (; i < ecnt; i += stride)
        atomicAdd(&g_cnt[__ldg(dstp + i)], 1);
}

// ---------------- K2a: per-block exclusive scan ----------------
__global__ void k_scan1(int n) {
    __shared__ int wsum[32];
    int tid = threadIdx.x, lane = tid & 31, wid = tid >> 5;
    int i = blockIdx.x * 1024 + tid;
    int orig = (i < n) ? g_cnt[i] : 0;
    int v = orig;
#pragma unroll
    for (int off = 1; off < 32; off <<= 1) {
        int t = __shfl_up_sync(0xffffffffu, v, off);
        if (lane >= off) v += t;
    }
    if (lane == 31) wsum[wid] = v;
    __syncthreads();
    if (wid == 0) {
        int s = wsum[lane];
#pragma unroll
        for (int off = 1; off < 32; off <<= 1) {
            int t = __shfl_up_sync(0xffffffffu, s, off);
            if (lane >= off) s += t;
        }
        wsum[lane] = s;
    }
    __syncthreads();
    int excl = v - orig + (wid > 0 ? wsum[wid - 1] : 0);
    if (i < n) g_start[i] = excl;
    if (tid == 0) g_bsum[blockIdx.x] = wsum[31];
}

// ---------------- K3: h = x @ W via HMMA (mma.sync m16n8k16), fused attention --
// 64-node tile; 8 warps = 4(node subtiles) x 2(col halves of 64).
// xs fp16 [64][PITCH], Ws fp16 transposed [col][k] [128][PITCH].
__global__ void __launch_bounds__(256, 3)
k_gemm(const float* __restrict__ x, const float* __restrict__ W,
       const float* __restrict__ attS, const float* __restrict__ attD, int n) {
    extern __shared__ __half smh[];
    __half* xs = smh;                     // [64][PITCH]
    __half* Ws = smh + 64 * PITCH;        // [128][PITCH] (Ws[c][k])

    int tid = threadIdx.x;
    int nodeBase = blockIdx.x * 64;

    // load x tile -> fp16 smem [node][k]
    for (int i = tid; i < 64 * 32; i += 256) {
        int nd = i >> 5, q = i & 31;
        float4 v = (nodeBase + nd < n) ? ((const float4*)x)[(nodeBase + nd) * 32 + q]
                                       : make_float4(0.f, 0.f, 0.f, 0.f);
        __half2 h0 = __floats2half2_rn(v.x, v.y);
        __half2 h1 = __floats2half2_rn(v.z, v.w);
        uint2 u;
        u.x = reinterpret_cast<unsigned&>(h0);
        u.y = reinterpret_cast<unsigned&>(h1);
        *(uint2*)&xs[nd * PITCH + q * 4] = u;
    }
    // load W transposed -> fp16 smem [col][k]
    for (int i = tid; i < INCH * HC; i += 256) {
        int k = i >> 7, c = i & 127;
        Ws[c * PITCH + k] = __float2half(W[i]);
    }
    __syncthreads();

    int lane = tid & 31, wid = tid >> 5;
    int wn = wid & 3;          // node subtile
    int wc = wid >> 2;         // col half (64 cols)
    int nb = wn * 16;
    int g  = lane >> 2;        // groupID
    int t  = lane & 3;         // threadID in group

    float acc[8][4];
#pragma unroll
    for (int c8 = 0; c8 < 8; c8++)
#pragma unroll
        for (int j = 0; j < 4; j++) acc[c8][j] = 0.f;

    const __half* xw = xs + nb * PITCH;
    const __half* ww = Ws + (wc * 64) * PITCH;

#pragma unroll
    for (int kc = 0; kc < 8; kc++) {
        int kb = kc * 16;
        unsigned a0 = *(const unsigned*)&xw[g * PITCH + kb + t * 2];
        unsigned a1 = *(const unsigned*)&xw[(g + 8) * PITCH + kb + t * 2];
        unsigned a2 = *(const unsigned*)&xw[g * PITCH + kb + t * 2 + 8];
        unsigned a3 = *(const unsigned*)&xw[(g + 8) * PITCH + kb + t * 2 + 8];
#pragma unroll
        for (int c8 = 0; c8 < 8; c8++) {
            unsigned b0 = *(const unsigned*)&ww[(c8 * 8 + g) * PITCH + kb + t * 2];
            unsigned b1 = *(const unsigned*)&ww[(c8 * 8 + g) * PITCH + kb + t * 2 + 8];
            asm("mma.sync.aligned.m16n8k16.row.col.f32.f16.f16.f32 "
                "{%0,%1,%2,%3}, {%4,%5,%6,%7}, {%8,%9}, {%0,%1,%2,%3};"
                : "+f"(acc[c8][0]), "+f"(acc[c8][1]), "+f"(acc[c8][2]), "+f"(acc[c8][3])
                : "r"(a0), "r"(a1), "r"(a2), "r"(a3), "r"(b0), "r"(b1));
        }
    }

    // epilogue: reassemble col-quads, store fp16 h, fused attention dots
    float ds[2] = {0.f, 0.f}, dd[2] = {0.f, 0.f};
#pragma unroll
    for (int c8 = 0; c8 < 8; c8++) {
        float a0 = acc[c8][0], a1 = acc[c8][1], a2 = acc[c8][2], a3 = acc[c8][3];
        float pa0 = __shfl_xor_sync(0xffffffffu, a0, 1);
        float pa1 = __shfl_xor_sync(0xffffffffu, a1, 1);
        float pa2 = __shfl_xor_sync(0xffffffffu, a2, 1);
        float pa3 = __shfl_xor_sync(0xffffffffu, a3, 1);
        float q0, q1, q2, q3;
        int node;
        if (!(t & 1)) { q0 = a0;  q1 = a1;  q2 = pa0; q3 = pa1; node = nodeBase + nb + g; }
        else          { q0 = pa2; q1 = pa3; q2 = a2;  q3 = a3;  node = nodeBase + nb + g + 8; }
        int quad = wc * 16 + c8 * 2 + (t >> 1);     // 4-col group index (0..31)
        if (node < n) {
            __half2 h01 = __floats2half2_rn(q0, q1);
            __half2 h23 = __floats2half2_rn(q2, q3);
            uint2 u;
            u.x = reinterpret_cast<unsigned&>(h01);
            u.y = reinterpret_cast<unsigned&>(h23);
            g_hh[node * 32 + quad] = u;
        }
        float4 As = ((const float4*)attS)[quad];
        float4 Ad = ((const float4*)attD)[quad];
        int hd = c8 >> 2;
        ds[hd] += q0 * As.x + q1 * As.y + q2 * As.z + q3 * As.w;
        dd[hd] += q0 * Ad.x + q1 * Ad.y + q2 * Ad.z + q3 * Ad.w;
    }
    // lanes (t, t^2) share a node & head pair: reduce, then t<2 writes
    ds[0] += __shfl_xor_sync(0xffffffffu, ds[0], 2);
    ds[1] += __shfl_xor_sync(0xffffffffu, ds[1], 2);
    dd[0] += __shfl_xor_sync(0xffffffffu, dd[0], 2);
    dd[1] += __shfl_xor_sync(0xffffffffu, dd[1], 2);
    int node = (t & 1) ? nodeBase + nb + g + 8 : nodeBase + nb + g;
    if (t < 2 && node < n) {
        *(float2*)&g_asrc[node * HEADS + wc * 2] = make_float2(ds[0], ds[1]);
        *(float2*)&g_adst[node * HEADS + wc * 2] = make_float2(dd[0], dd[1]);
    }
}

// ---------------- K2b: scan of block sums ----------------
__global__ void k_scan2(int nb) {
    __shared__ int t0;
    int tid = threadIdx.x, lane = tid & 31, w = tid >> 5;
    int orig = (tid < nb) ? g_bsum[tid] : 0;
    int v = orig;
#pragma unroll
    for (int off = 1; off < 32; off <<= 1) {
        int t = __shfl_up_sync(0xffffffffu, v, off);
        if (lane >= off) v += t;
    }
    if (w == 0 && lane == 31) t0 = v;
    __syncthreads();
    int incl = v + (w == 1 ? t0 : 0);
    if (tid < nb) g_bsum[tid] = incl - orig;   // exclusive
}

// ---------------- K2c: add block offsets, init cursors ----------------
__global__ void k_scan3(int n) {
    int i = blockIdx.x * 1024 + threadIdx.x;
    if (i < n) {
        int v = g_start[i] + g_bsum[blockIdx.x];
        g_start[i] = v;
        g_cur[i] = v;
    }
}

// ---------------- K4: scatter src into dst-sorted order (4B/edge) ----------------
__global__ void k_scatter(const int* __restrict__ srcp,
                          const int* __restrict__ dstp, int ecnt) {
    int i = blockIdx.x * blockDim.x + threadIdx.x;
    int stride = gridDim.x * blockDim.x;
    for (; i < ecnt; i += stride) {
        int d = __ldg(dstp + i);
        int s = __ldg(srcp + i);
        int pos = atomicAdd(&g_cur[d], 1);
        g_ssrc[pos] = s;
    }
}

// ---------------- K5: warp-per-dst aggregation + fused epilogue ----------------
__device__ __forceinline__ void fma_h16(float4& acc, float w, uint2 u) {
    __half2 lo = reinterpret_cast<__half2&>(u.x);
    __half2 hi = reinterpret_cast<__half2&>(u.y);
    float2 f01 = __half22float2(lo);
    float2 f23 = __half22float2(hi);
    acc.x += w * f01.x; acc.y += w * f01.y;
    acc.z += w * f23.x; acc.w += w * f23.y;
}

__global__ void k_agg(float* __restrict__ out, const float* __restrict__ bias,
                      int n) {
    int lane = threadIdx.x & 31;
    int node = (blockIdx.x * blockDim.x + threadIdx.x) >> 5;
    if (node >= n) return;
    int head = lane >> 3;

    float aD = __ldg(&g_adst[node * HEADS + head]);
    int start = __ldg(&g_start[node]);
    int deg   = __ldg(&g_cnt[node]);
    int end   = start + deg;

    float4 acc = make_float4(0.f, 0.f, 0.f, 0.f);
    float ssum = 0.f;

    int e = start;
    for (; e + 8 <= end; e += 8) {
        int s[8];
#pragma unroll
        for (int j = 0; j < 8; j++) s[j] = __ldg(&g_ssrc[e + j]);
        float a[8];
#pragma unroll
        for (int j = 0; j < 8; j++)
            a[j] = __ldg(&g_asrc[s[j] * HEADS + head]) + aD;
        uint2 u[8];
#pragma unroll
        for (int j = 0; j < 8; j++)
            u[j] = __ldg(&g_hh[s[j] * 32 + lane]);
#pragma unroll
        for (int j = 0; j < 8; j++) {
            float w = __expf(a[j] > 0.f ? a[j] : NEG * a[j]);
            ssum += w;
            fma_h16(acc, w, u[j]);
        }
    }
    for (; e < end; e++) {
        int s = __ldg(&g_ssrc[e]);
        float a = __ldg(&g_asrc[s * HEADS + head]) + aD;
        float w = __expf(a > 0.f ? a : NEG * a);
        uint2 u = __ldg(&g_hh[s * 32 + lane]);
        ssum += w;
        fma_h16(acc, w, u);
    }

    // self loop (fp16 h like all other edges)
    {
        float a = __ldg(&g_asrc[node * HEADS + head]) + aD;
        float w = __expf(a > 0.f ? a : NEG * a);
        uint2 u = g_hh[node * 32 + lane];
        ssum += w;
        fma_h16(acc, w, u);
    }

    float inv = 1.f / ssum;
    float4 b = ((const float4*)bias)[lane];
    float v0 = acc.x * inv + b.x;
    float v1 = acc.y * inv + b.y;
    float v2 = acc.z * inv + b.z;
    float v3 = acc.w * inv + b.w;
    v0 = v0 > 0.f ? v0 : expm1f(v0);
    v1 = v1 > 0.f ? v1 : expm1f(v1);
    v2 = v2 > 0.f ? v2 : expm1f(v2);
    v3 = v3 > 0.f ? v3 : expm1f(v3);
    ((float4*)out)[node * 32 + lane] = make_float4(v0, v1, v2, v3);
}

// ---------------- launch ----------------
extern "C" void kernel_launch(void* const* d_in, const int* in_sizes, int n_in,
                              void* d_out, int out_size) {
    const float* x    = (const float*)d_in[0];
    const int*   ei   = (const int*)d_in[1];      // int32 (jax demotes int64)
    const float* W    = (const float*)d_in[2];
    const float* attS = (const float*)d_in[3];
    const float* attD = (const float*)d_in[4];
    const float* bias = (const float*)d_in[5];
    float*       out  = (float*)d_out;

    int n    = in_sizes[0] / INCH;     // 50000
    int ecnt = in_sizes[1] / 2;        // 1600000
    int nb   = (n + 1023) / 1024;      // 49

    const int smemBytes = (64 * PITCH + 128 * PITCH) * (int)sizeof(__half); // 52224
    cudaFuncSetAttribute(k_gemm, cudaFuncAttributeMaxDynamicSharedMemorySize,
                         smemBytes);

    // order chosen so the ncu bounded capture lands on k_gemm (4th launch)
    k_zero<<<64, 1024>>>(n);
    k_hist<<<2048, 256>>>(ei + ecnt, ecnt);
    k_scan1<<<nb, 1024>>>(n);
    k_gemm<<<(n + 63) / 64, 256, smemBytes>>>(x, W, attS, attD, n);
    k_scan2<<<1, 64>>>(nb);
    k_scan3<<<nb, 1024>>>(n);
    k_scatter<<<2048, 256>>>(ei, ei + ecnt, ecnt);
    k_agg<<<(n + 7) / 8, 256>>>(out, bias, n);
}